// round 5
// baseline (speedup 1.0000x reference)
#include <cuda_runtime.h>
#include <cstdint>

// Problem constants
#define B_   2
#define S_   2048
#define D_   1024
#define H_   16
#define DH_  64
#define N_   (B_ * S_)   // 4096 tokens
#define K_   1024

typedef unsigned long long u64t;

// ---------------------------------------------------------------------------
// Scratch (device globals — no allocation allowed)
// ---------------------------------------------------------------------------
__device__ float g_q[B_ * H_ * S_ * DH_];   // [b][h][s][dh]
__device__ float g_k[B_ * H_ * S_ * DH_];
__device__ float g_v[B_ * H_ * S_ * DH_];
__device__ float g_att[N_ * D_];            // [n][h*64+dh]

// ---------------------------------------------------------------------------
// Packed f32x2 helpers (sm_100-family PTX, plain target)
// ---------------------------------------------------------------------------
__device__ __forceinline__ void fma2(u64t& c, u64t a, u64t b) {
    asm("fma.rn.f32x2 %0, %1, %2, %0;" : "+l"(c) : "l"(a), "l"(b));
}
__device__ __forceinline__ u64t mul2(u64t a, u64t b) {
    u64t r; asm("mul.rn.f32x2 %0, %1, %2;" : "=l"(r) : "l"(a), "l"(b)); return r;
}
__device__ __forceinline__ u64t pk2(float x, float y) {
    u64t r; asm("mov.b64 %0, {%1, %2};" : "=l"(r) : "f"(x), "f"(y)); return r;
}
__device__ __forceinline__ float2 up2(u64t a) {
    float2 r; asm("mov.b64 {%0, %1}, %2;" : "=f"(r.x), "=f"(r.y) : "l"(a)); return r;
}

// ---------------------------------------------------------------------------
// FFMA2 TN GEMM: C[n,o] = sum_k A[n,k]*W[o,k] + bias[o]
// Tile 128x64, BK=16, 256 threads. A dup-paired in smem, W pairs along o.
// scatter==1 -> Q/K/V head-major layout, else row-major.
// ---------------------------------------------------------------------------
__global__ void __launch_bounds__(256)
gemm_f32x2(const float* __restrict__ A, const float* __restrict__ W,
           const float* __restrict__ bias, float* __restrict__ C, int scatter)
{
    __shared__ float2 As2[16 * 128];   // [k][m] duplicated pairs (a,a)
    __shared__ float  Bs[16 * 68];     // [k][o] scalar, padded

    const int t  = threadIdx.x;
    const int bn = blockIdx.x;   // o block (16)
    const int bm = blockIdx.y;   // token block (32)

    const int tm = t >> 4;       // 0..15 -> rows 8*tm..+7
    const int tx = t & 15;       // cols 4*tx..+3 (2 pairs)

    // global load mapping
    const int ar = t >> 1;              // A row 0..127
    const int af = (t & 1) * 2;         // A float4 index base (0 or 2)
    const int wr = t >> 2;              // W row 0..63
    const int wf = t & 3;               // W float4 index

    const float* Ag = A + (size_t)(bm * 128 + ar) * K_ + af * 4;
    const float* Wg = W + (size_t)(bn * 64 + wr) * K_ + wf * 4;

    u64t acc[8][2];
#pragma unroll
    for (int i = 0; i < 8; i++) { acc[i][0] = 0ULL; acc[i][1] = 0ULL; }

    float4 pa0 = *(const float4*)(Ag);
    float4 pa1 = *(const float4*)(Ag + 4);
    float4 pw  = *(const float4*)(Wg);

    for (int c = 0; c < 64; c++) {
        __syncthreads();
        {
            const int k0 = af * 4;
            As2[(k0 + 0) * 128 + ar] = make_float2(pa0.x, pa0.x);
            As2[(k0 + 1) * 128 + ar] = make_float2(pa0.y, pa0.y);
            As2[(k0 + 2) * 128 + ar] = make_float2(pa0.z, pa0.z);
            As2[(k0 + 3) * 128 + ar] = make_float2(pa0.w, pa0.w);
            As2[(k0 + 4) * 128 + ar] = make_float2(pa1.x, pa1.x);
            As2[(k0 + 5) * 128 + ar] = make_float2(pa1.y, pa1.y);
            As2[(k0 + 6) * 128 + ar] = make_float2(pa1.z, pa1.z);
            As2[(k0 + 7) * 128 + ar] = make_float2(pa1.w, pa1.w);
            const int kw = wf * 4;
            Bs[(kw + 0) * 68 + wr] = pw.x;
            Bs[(kw + 1) * 68 + wr] = pw.y;
            Bs[(kw + 2) * 68 + wr] = pw.z;
            Bs[(kw + 3) * 68 + wr] = pw.w;
        }
        __syncthreads();
        if (c < 63) {
            const float* An = Ag + (size_t)(c + 1) * 16;
            pa0 = *(const float4*)(An);
            pa1 = *(const float4*)(An + 4);
            pw  = *(const float4*)(Wg + (size_t)(c + 1) * 16);
        }
#pragma unroll
        for (int kk = 0; kk < 16; kk++) {
            u64t ad[8];
#pragma unroll
            for (int i = 0; i < 8; i++)
                ad[i] = *(const u64t*)&As2[kk * 128 + 8 * tm + i];
            const u64t w0 = *(const u64t*)&Bs[kk * 68 + 4 * tx];
            const u64t w1 = *(const u64t*)&Bs[kk * 68 + 4 * tx + 2];
#pragma unroll
            for (int i = 0; i < 8; i++) {
                fma2(acc[i][0], ad[i], w0);
                fma2(acc[i][1], ad[i], w1);
            }
        }
    }

    // Epilogue
#pragma unroll
    for (int i = 0; i < 8; i++) {
        const int n = bm * 128 + 8 * tm + i;
#pragma unroll
        for (int jp = 0; jp < 2; jp++) {
            const int col = bn * 64 + 4 * tx + 2 * jp;
            float2 v = up2(acc[i][jp]);
            v.x += bias[col];
            v.y += bias[col + 1];
            if (scatter) {
                const int b  = n >> 11;
                const int s  = n & (S_ - 1);
                const int hh = col >> 6;
                const int dh = col & 63;
                *(float2*)(C + (((size_t)(b * H_ + hh)) * S_ + s) * DH_ + dh) = v;
            } else {
                *(float2*)(C + (size_t)n * D_ + col) = v;
            }
        }
    }
}

// ---------------------------------------------------------------------------
// Flash attention with FFMA2 inner loops.
// smem: Qt2[dh][row] dup pairs, Ps2[row][col] dup pairs, Kt[dh][col], Vs[row][dh]
// ---------------------------------------------------------------------------
#define FP   68
#define PSR  66   // Ps2 row stride in pairs

#define OFF_QT2 0
#define OFF_PS2 32768
#define OFF_KT  (32768 + 33792)
#define OFF_VS  (32768 + 33792 + 17408)
#define OFF_MSK (32768 + 33792 + 17408 + 17408)
#define FLASH_SMEM (OFF_MSK + 256)

__global__ void __launch_bounds__(256)
flash_kernel(const int* __restrict__ mask, float* __restrict__ out)
{
    extern __shared__ char smc[];
    float2* Qt2 = (float2*)(smc + OFF_QT2);   // [64][64] dup pairs
    float2* Ps2 = (float2*)(smc + OFF_PS2);   // [64][PSR] dup pairs
    float*  Kt  = (float*) (smc + OFF_KT);    // [64][68]
    float*  Vs  = (float*) (smc + OFF_VS);    // [64][68]
    int*    msk = (int*)   (smc + OFF_MSK);

    const int qb = blockIdx.x;
    const int h  = blockIdx.y;
    const int b  = blockIdx.z;

    const float* Qg = g_q + ((size_t)(b * H_ + h)) * S_ * DH_;
    const float* Kg = g_k + ((size_t)(b * H_ + h)) * S_ * DH_;
    const float* Vg = g_v + ((size_t)(b * H_ + h)) * S_ * DH_;

    const int t  = threadIdx.x;
    const int tx = t & 15;
    const int ty = t >> 4;
    const int lrow = t >> 2;
    const int lq   = t & 3;

    // Load Q tile once: dup-paired transposed Qt2[dh][row]
#pragma unroll
    for (int i = 0; i < 4; i++) {
        const int dh0 = 16 * i + 4 * lq;
        float4 q4 = *(const float4*)(Qg + (size_t)(qb * 64 + lrow) * DH_ + dh0);
        Qt2[(dh0 + 0) * 64 + lrow] = make_float2(q4.x, q4.x);
        Qt2[(dh0 + 1) * 64 + lrow] = make_float2(q4.y, q4.y);
        Qt2[(dh0 + 2) * 64 + lrow] = make_float2(q4.z, q4.z);
        Qt2[(dh0 + 3) * 64 + lrow] = make_float2(q4.w, q4.w);
    }

    float m_i[4], l_i[4];
    u64t  o2[4][2];
#pragma unroll
    for (int i = 0; i < 4; i++) {
        m_i[i] = -1e30f; l_i[i] = 0.f;
        o2[i][0] = 0ULL; o2[i][1] = 0ULL;
    }

    for (int kb = 0; kb < S_ / 64; kb++) {
        __syncthreads();
#pragma unroll
        for (int i = 0; i < 4; i++) {
            const int dh0 = 16 * i + 4 * lq;
            float4 k4 = *(const float4*)(Kg + (size_t)(kb * 64 + lrow) * DH_ + dh0);
            Kt[(dh0 + 0) * FP + lrow] = k4.x;
            Kt[(dh0 + 1) * FP + lrow] = k4.y;
            Kt[(dh0 + 2) * FP + lrow] = k4.z;
            Kt[(dh0 + 3) * FP + lrow] = k4.w;
            float4 v4 = *(const float4*)(Vg + (size_t)(kb * 64 + lrow) * DH_ + dh0);
            *(float4*)&Vs[lrow * FP + dh0] = v4;
        }
        if (t < 64) msk[t] = mask[b * S_ + kb * 64 + t];
        __syncthreads();

        // Scores: s2[i][jp] pairs over key columns (4tx+2jp, +1)
        u64t s2[4][2];
#pragma unroll
        for (int i = 0; i < 4; i++) { s2[i][0] = 0ULL; s2[i][1] = 0ULL; }
#pragma unroll 8
        for (int kk = 0; kk < 64; kk++) {
            u64t qd[4];
#pragma unroll
            for (int i = 0; i < 4; i++)
                qd[i] = *(const u64t*)&Qt2[kk * 64 + 4 * ty + i];
            const u64t k0 = *(const u64t*)&Kt[kk * FP + 4 * tx];
            const u64t k1 = *(const u64t*)&Kt[kk * FP + 4 * tx + 2];
#pragma unroll
            for (int i = 0; i < 4; i++) {
                fma2(s2[i][0], qd[i], k0);
                fma2(s2[i][1], qd[i], k1);
            }
        }

        // Unpack, scale + mask
        float s[4][4];
#pragma unroll
        for (int i = 0; i < 4; i++) {
            float2 sa = up2(s2[i][0]);
            float2 sb = up2(s2[i][1]);
            s[i][0] = sa.x; s[i][1] = sa.y; s[i][2] = sb.x; s[i][3] = sb.y;
        }
#pragma unroll
        for (int j = 0; j < 4; j++) {
            const bool ok = msk[4 * tx + j] != 0;
#pragma unroll
            for (int i = 0; i < 4; i++)
                s[i][j] = ok ? s[i][j] * 0.125f : -1e9f;
        }

        // Online softmax + dup-paired P store
#pragma unroll
        for (int i = 0; i < 4; i++) {
            float rmax = fmaxf(fmaxf(s[i][0], s[i][1]), fmaxf(s[i][2], s[i][3]));
#pragma unroll
            for (int d = 1; d <= 8; d <<= 1)
                rmax = fmaxf(rmax, __shfl_xor_sync(0xffffffffu, rmax, d));
            const float mnew  = fmaxf(m_i[i], rmax);
            const float alpha = __expf(m_i[i] - mnew);
            float rsum = 0.f;
#pragma unroll
            for (int j = 0; j < 4; j++) {
                s[i][j] = __expf(s[i][j] - mnew);
                rsum += s[i][j];
            }
#pragma unroll
            for (int d = 1; d <= 8; d <<= 1)
                rsum += __shfl_xor_sync(0xffffffffu, rsum, d);
            l_i[i] = l_i[i] * alpha + rsum;
            m_i[i] = mnew;
            const u64t a2 = pk2(alpha, alpha);
            o2[i][0] = mul2(o2[i][0], a2);
            o2[i][1] = mul2(o2[i][1], a2);
            const int pr = (4 * ty + i) * PSR + 4 * tx;
            *(float4*)&Ps2[pr]     = make_float4(s[i][0], s[i][0], s[i][1], s[i][1]);
            *(float4*)&Ps2[pr + 2] = make_float4(s[i][2], s[i][2], s[i][3], s[i][3]);
        }
        __syncthreads();

        // O += P @ V : pairs over output dh (4tx+2dp, +1)
#pragma unroll 8
        for (int jj = 0; jj < 64; jj++) {
            u64t pd[4];
#pragma unroll
            for (int i = 0; i < 4; i++)
                pd[i] = *(const u64t*)&Ps2[(4 * ty + i) * PSR + jj];
            const u64t v0 = *(const u64t*)&Vs[jj * FP + 4 * tx];
            const u64t v1 = *(const u64t*)&Vs[jj * FP + 4 * tx + 2];
#pragma unroll
            for (int i = 0; i < 4; i++) {
                fma2(o2[i][0], pd[i], v0);
                fma2(o2[i][1], pd[i], v1);
            }
        }
    }

    // Epilogue
#pragma unroll
    for (int i = 0; i < 4; i++) {
        const float inv = 1.f / l_i[i];
        const int sg = qb * 64 + 4 * ty + i;
#pragma unroll
        for (int dp = 0; dp < 2; dp++) {
            float2 v = up2(o2[i][dp]);
            v.x *= inv; v.y *= inv;
            *(float2*)(out + ((size_t)(b * S_ + sg)) * D_ + h * DH_ + 4 * tx + 2 * dp) = v;
        }
    }
}

// ---------------------------------------------------------------------------
// Launch
// ---------------------------------------------------------------------------
extern "C" void kernel_launch(void* const* d_in, const int* in_sizes, int n_in,
                              void* d_out, int out_size)
{
    (void)in_sizes; (void)n_in; (void)out_size;
    const float* x    = (const float*)d_in[0];
    const int*   mask = (const int*)  d_in[1];
    const float* Wq   = (const float*)d_in[2];
    const float* bq   = (const float*)d_in[3];
    const float* Wk   = (const float*)d_in[4];
    const float* bk   = (const float*)d_in[5];
    const float* Wv   = (const float*)d_in[6];
    const float* bv   = (const float*)d_in[7];
    const float* Wo   = (const float*)d_in[8];
    const float* bo   = (const float*)d_in[9];
    float* out = (float*)d_out;

    float *qp, *kp, *vp, *ap;
    cudaGetSymbolAddress((void**)&qp, g_q);
    cudaGetSymbolAddress((void**)&kp, g_k);
    cudaGetSymbolAddress((void**)&vp, g_v);
    cudaGetSymbolAddress((void**)&ap, g_att);

    static int attr_done = 0;
    if (!attr_done) {
        cudaFuncSetAttribute(flash_kernel,
                             cudaFuncAttributeMaxDynamicSharedMemorySize, FLASH_SMEM);
        attr_done = 1;
    }

    dim3 gg(D_ / 64, N_ / 128);   // (16, 32)
    gemm_f32x2<<<gg, 256>>>(x, Wq, bq, qp, 1);
    gemm_f32x2<<<gg, 256>>>(x, Wk, bk, kp, 1);
    gemm_f32x2<<<gg, 256>>>(x, Wv, bv, vp, 1);

    flash_kernel<<<dim3(S_ / 64, H_, B_), 256, FLASH_SMEM>>>(mask, ap);

    gemm_f32x2<<<gg, 256>>>(ap, Wo, bo, out, 0);
}

// round 7
// speedup vs baseline: 1.1061x; 1.1061x over previous
#include <cuda_runtime.h>
#include <cstdint>

// Problem constants
#define B_   2
#define S_   2048
#define D_   1024
#define H_   16
#define DH_  64
#define N_   (B_ * S_)   // 4096 tokens
#define K_   1024

typedef unsigned long long u64t;

// ---------------------------------------------------------------------------
// Scratch (device globals — no allocation allowed)
// ---------------------------------------------------------------------------
__device__ float g_q[B_ * H_ * S_ * DH_];   // [b][h][s][dh]
__device__ float g_k[B_ * H_ * S_ * DH_];
__device__ float g_v[B_ * H_ * S_ * DH_];
__device__ float g_att[N_ * D_];            // [n][h*64+dh]

// ---------------------------------------------------------------------------
// Packed f32x2 helpers
// ---------------------------------------------------------------------------
__device__ __forceinline__ void fma2(u64t& c, u64t a, u64t b) {
    asm("fma.rn.f32x2 %0, %1, %2, %0;" : "+l"(c) : "l"(a), "l"(b));
}
__device__ __forceinline__ u64t mul2(u64t a, u64t b) {
    u64t r; asm("mul.rn.f32x2 %0, %1, %2;" : "=l"(r) : "l"(a), "l"(b)); return r;
}
__device__ __forceinline__ u64t pk2(float x, float y) {
    u64t r; asm("mov.b64 %0, {%1, %2};" : "=l"(r) : "f"(x), "f"(y)); return r;
}
__device__ __forceinline__ float2 up2(u64t a) {
    float2 r; asm("mov.b64 {%0, %1}, %2;" : "=f"(r.x), "=f"(r.y) : "l"(a)); return r;
}

// ---------------------------------------------------------------------------
// FFMA2 TN GEMM: C[n,o] = sum_k A[n,k]*W[o,k] + bias[o]
// Tile 128x128, BK=16, 256 threads (16 rg x 16 cg), 8x8 microtile.
// A dup-paired in smem (cheap: 16KB/chunk); W scalar pairs along o.
// ---------------------------------------------------------------------------
#define MP2 130   // As2 k-row stride in float2
#define WP  132   // Ws  k-row stride in float

__global__ void __launch_bounds__(256, 2)
gemm2(const float* __restrict__ A, const float* __restrict__ W,
      const float* __restrict__ bias, float* __restrict__ C, int scatter)
{
    __shared__ float2 As2[16 * MP2];   // [k][m] dup pairs
    __shared__ float  Ws[16 * WP];     // [k][o]

    const int t  = threadIdx.x;
    const int bn = blockIdx.x;   // o block (8)
    const int bm = blockIdx.y;   // token block (32)
    const int rg = t >> 4;       // rows 8rg..+7
    const int cg = t & 15;       // cols 8cg..+7

    const int lr = t >> 1;          // 0..127
    const int lk = (t & 1) * 8;     // 0 or 8

    const float* Ag = A + (size_t)(bm * 128 + lr) * K_ + lk;
    const float* Wg = W + (size_t)(bn * 128 + lr) * K_ + lk;

    u64t acc[8][4];
#pragma unroll
    for (int r = 0; r < 8; r++)
#pragma unroll
        for (int p = 0; p < 4; p++) acc[r][p] = 0ULL;

    float4 pa0 = *(const float4*)(Ag);
    float4 pa1 = *(const float4*)(Ag + 4);
    float4 pw0 = *(const float4*)(Wg);
    float4 pw1 = *(const float4*)(Wg + 4);

    for (int c = 0; c < 64; c++) {
        __syncthreads();
        As2[(lk + 0) * MP2 + lr] = make_float2(pa0.x, pa0.x);
        As2[(lk + 1) * MP2 + lr] = make_float2(pa0.y, pa0.y);
        As2[(lk + 2) * MP2 + lr] = make_float2(pa0.z, pa0.z);
        As2[(lk + 3) * MP2 + lr] = make_float2(pa0.w, pa0.w);
        As2[(lk + 4) * MP2 + lr] = make_float2(pa1.x, pa1.x);
        As2[(lk + 5) * MP2 + lr] = make_float2(pa1.y, pa1.y);
        As2[(lk + 6) * MP2 + lr] = make_float2(pa1.z, pa1.z);
        As2[(lk + 7) * MP2 + lr] = make_float2(pa1.w, pa1.w);
        Ws[(lk + 0) * WP + lr] = pw0.x;
        Ws[(lk + 1) * WP + lr] = pw0.y;
        Ws[(lk + 2) * WP + lr] = pw0.z;
        Ws[(lk + 3) * WP + lr] = pw0.w;
        Ws[(lk + 4) * WP + lr] = pw1.x;
        Ws[(lk + 5) * WP + lr] = pw1.y;
        Ws[(lk + 6) * WP + lr] = pw1.z;
        Ws[(lk + 7) * WP + lr] = pw1.w;
        __syncthreads();
        if (c < 63) {
            const float* An = Ag + (size_t)(c + 1) * 16;
            const float* Wn = Wg + (size_t)(c + 1) * 16;
            pa0 = *(const float4*)(An);
            pa1 = *(const float4*)(An + 4);
            pw0 = *(const float4*)(Wn);
            pw1 = *(const float4*)(Wn + 4);
        }
#pragma unroll
        for (int kk = 0; kk < 16; kk++) {
            u64t a[8], w[4];
            {
                const ulonglong2* ap = (const ulonglong2*)&As2[kk * MP2 + 8 * rg];
                ulonglong2 a01 = ap[0], a23 = ap[1], a45 = ap[2], a67 = ap[3];
                a[0] = a01.x; a[1] = a01.y; a[2] = a23.x; a[3] = a23.y;
                a[4] = a45.x; a[5] = a45.y; a[6] = a67.x; a[7] = a67.y;
                const ulonglong2* wp = (const ulonglong2*)&Ws[kk * WP + 8 * cg];
                ulonglong2 w01 = wp[0], w23 = wp[1];
                w[0] = w01.x; w[1] = w01.y; w[2] = w23.x; w[3] = w23.y;
            }
#pragma unroll
            for (int r = 0; r < 8; r++) {
                fma2(acc[r][0], a[r], w[0]);
                fma2(acc[r][1], a[r], w[1]);
                fma2(acc[r][2], a[r], w[2]);
                fma2(acc[r][3], a[r], w[3]);
            }
        }
    }

    // Epilogue
#pragma unroll
    for (int r = 0; r < 8; r++) {
        const int n = bm * 128 + 8 * rg + r;
#pragma unroll
        for (int p = 0; p < 4; p++) {
            const int col = bn * 128 + 8 * cg + 2 * p;
            float2 v = up2(acc[r][p]);
            v.x += bias[col];
            v.y += bias[col + 1];
            if (scatter) {
                const int b  = n >> 11;
                const int s  = n & (S_ - 1);
                const int hh = col >> 6;
                const int dh = col & 63;
                *(float2*)(C + (((size_t)(b * H_ + hh)) * S_ + s) * DH_ + dh) = v;
            } else {
                *(float2*)(C + (size_t)n * D_ + col) = v;
            }
        }
    }
}

// ---------------------------------------------------------------------------
// Flash attention, FFMA2, 128-row Q tile, 128-key blocks, 8x8 microtile.
// smem: Qt2[dh][row] dup pairs (write-once), Ps[row][col] scalar,
//       Kt[dh][key], Vs[key][dh]
// ---------------------------------------------------------------------------
#define QP2 130   // Qt2 dh-row stride (float2)
#define PSP 132   // Ps row stride (float)
#define KTP 132   // Kt dh-row stride (float)
#define VSP 68    // Vs key-row stride (float)

#define OFF_QT2 0
#define OFF_PS  (OFF_QT2 + 64 * QP2 * 8)          // 66560
#define OFF_KT  (OFF_PS  + 128 * PSP * 4)         // 134144
#define OFF_VS  (OFF_KT  + 64 * KTP * 4)          // 167936
#define OFF_MSK (OFF_VS  + 128 * VSP * 4)         // 202752
#define FLASH_SMEM (OFF_MSK + 512)                // 203264

__global__ void __launch_bounds__(256)
flash_kernel(const int* __restrict__ mask, float* __restrict__ out)
{
    extern __shared__ char smc[];
    float2* Qt2 = (float2*)(smc + OFF_QT2);
    float*  Ps  = (float*) (smc + OFF_PS);
    float*  Kt  = (float*) (smc + OFF_KT);
    float*  Vs  = (float*) (smc + OFF_VS);
    int*    msk = (int*)   (smc + OFF_MSK);

    const int qb = blockIdx.x;
    const int h  = blockIdx.y;
    const int b  = blockIdx.z;

    const float* Qg = g_q + ((size_t)(b * H_ + h)) * S_ * DH_;
    const float* Kg = g_k + ((size_t)(b * H_ + h)) * S_ * DH_;
    const float* Vg = g_v + ((size_t)(b * H_ + h)) * S_ * DH_;

    const int t  = threadIdx.x;
    const int rg = t >> 4;        // Q rows 8rg..+7
    const int cg = t & 15;        // QK cols 8cg..+7; PV dh cols 4cg..+3

    const int lr  = t >> 1;       // 0..127
    const int ld0 = (t & 1) * 32; // dh half

    // Load Q tile once: Qt2[dh][row] dup pairs
#pragma unroll
    for (int j = 0; j < 8; j++) {
        float4 q4 = *(const float4*)(Qg + (size_t)(qb * 128 + lr) * DH_ + ld0 + 4 * j);
        Qt2[(ld0 + 4 * j + 0) * QP2 + lr] = make_float2(q4.x, q4.x);
        Qt2[(ld0 + 4 * j + 1) * QP2 + lr] = make_float2(q4.y, q4.y);
        Qt2[(ld0 + 4 * j + 2) * QP2 + lr] = make_float2(q4.z, q4.z);
        Qt2[(ld0 + 4 * j + 3) * QP2 + lr] = make_float2(q4.w, q4.w);
    }

    float m_i[8], l_i[8];
    u64t  o2[8][2];
#pragma unroll
    for (int r = 0; r < 8; r++) {
        m_i[r] = -1e30f; l_i[r] = 0.f;
        o2[r][0] = 0ULL; o2[r][1] = 0ULL;
    }

    for (int kb = 0; kb < S_ / 128; kb++) {
        __syncthreads();
        // Load K (transposed) and V (direct) for 128 keys
#pragma unroll
        for (int j = 0; j < 8; j++) {
            float4 k4 = *(const float4*)(Kg + (size_t)(kb * 128 + lr) * DH_ + ld0 + 4 * j);
            Kt[(ld0 + 4 * j + 0) * KTP + lr] = k4.x;
            Kt[(ld0 + 4 * j + 1) * KTP + lr] = k4.y;
            Kt[(ld0 + 4 * j + 2) * KTP + lr] = k4.z;
            Kt[(ld0 + 4 * j + 3) * KTP + lr] = k4.w;
            float4 v4 = *(const float4*)(Vg + (size_t)(kb * 128 + lr) * DH_ + ld0 + 4 * j);
            *(float4*)&Vs[lr * VSP + ld0 + 4 * j] = v4;
        }
        if (t < 128) msk[t] = mask[b * S_ + kb * 128 + t];
        __syncthreads();

        // Scores: s2[r][p] pairs over key cols (8cg+2p, +1)
        u64t s2[8][4];
#pragma unroll
        for (int r = 0; r < 8; r++)
#pragma unroll
            for (int p = 0; p < 4; p++) s2[r][p] = 0ULL;

#pragma unroll 4
        for (int kk = 0; kk < 64; kk++) {
            u64t qd[8], kp[4];
            {
                const ulonglong2* qp = (const ulonglong2*)&Qt2[kk * QP2 + 8 * rg];
                ulonglong2 q01 = qp[0], q23 = qp[1], q45 = qp[2], q67 = qp[3];
                qd[0] = q01.x; qd[1] = q01.y; qd[2] = q23.x; qd[3] = q23.y;
                qd[4] = q45.x; qd[5] = q45.y; qd[6] = q67.x; qd[7] = q67.y;
                const ulonglong2* kpp = (const ulonglong2*)&Kt[kk * KTP + 8 * cg];
                ulonglong2 k01 = kpp[0], k23 = kpp[1];
                kp[0] = k01.x; kp[1] = k01.y; kp[2] = k23.x; kp[3] = k23.y;
            }
#pragma unroll
            for (int r = 0; r < 8; r++) {
                fma2(s2[r][0], qd[r], kp[0]);
                fma2(s2[r][1], qd[r], kp[1]);
                fma2(s2[r][2], qd[r], kp[2]);
                fma2(s2[r][3], qd[r], kp[3]);
            }
        }

        // Unpack, scale + mask
        float s[8][8];
#pragma unroll
        for (int r = 0; r < 8; r++)
#pragma unroll
            for (int p = 0; p < 4; p++) {
                float2 v = up2(s2[r][p]);
                s[r][2 * p]     = v.x;
                s[r][2 * p + 1] = v.y;
            }
#pragma unroll
        for (int j = 0; j < 8; j++) {
            const bool ok = msk[8 * cg + j] != 0;
#pragma unroll
            for (int r = 0; r < 8; r++)
                s[r][j] = ok ? s[r][j] * 0.125f : -1e9f;
        }

        // Online softmax per row (reduce across 16 cg lanes) + scalar P store
#pragma unroll
        for (int r = 0; r < 8; r++) {
            float rmax = s[r][0];
#pragma unroll
            for (int j = 1; j < 8; j++) rmax = fmaxf(rmax, s[r][j]);
#pragma unroll
            for (int d = 1; d <= 8; d <<= 1)
                rmax = fmaxf(rmax, __shfl_xor_sync(0xffffffffu, rmax, d));
            const float mnew  = fmaxf(m_i[r], rmax);
            const float alpha = __expf(m_i[r] - mnew);
            float rsum = 0.f;
#pragma unroll
            for (int j = 0; j < 8; j++) {
                s[r][j] = __expf(s[r][j] - mnew);
                rsum += s[r][j];
            }
#pragma unroll
            for (int d = 1; d <= 8; d <<= 1)
                rsum += __shfl_xor_sync(0xffffffffu, rsum, d);
            l_i[r] = l_i[r] * alpha + rsum;
            m_i[r] = mnew;
            const u64t a2 = pk2(alpha, alpha);
            o2[r][0] = mul2(o2[r][0], a2);
            o2[r][1] = mul2(o2[r][1], a2);
            float* pr = &Ps[(8 * rg + r) * PSP + 8 * cg];
            *(float4*)(pr)     = make_float4(s[r][0], s[r][1], s[r][2], s[r][3]);
            *(float4*)(pr + 4) = make_float4(s[r][4], s[r][5], s[r][6], s[r][7]);
        }
        __syncthreads();

        // O += P @ V  (k over 128 keys; dh cols 4cg..+3 => 2 pairs)
#pragma unroll 4
        for (int jj = 0; jj < 128; jj++) {
            const ulonglong2 vv = *(const ulonglong2*)&Vs[jj * VSP + 4 * cg];
            const float* pcol = &Ps[8 * rg * PSP + jj];
#pragma unroll
            for (int r = 0; r < 8; r++) {
                const float p = pcol[r * PSP];
                const u64t pp = pk2(p, p);
                fma2(o2[r][0], pp, vv.x);
                fma2(o2[r][1], pp, vv.y);
            }
        }
    }

    // Epilogue
#pragma unroll
    for (int r = 0; r < 8; r++) {
        const float inv = 1.f / l_i[r];
        const int sg = qb * 128 + 8 * rg + r;
        float2 v0 = up2(o2[r][0]);
        float2 v1 = up2(o2[r][1]);
        float4 v = make_float4(v0.x * inv, v0.y * inv, v1.x * inv, v1.y * inv);
        *(float4*)(out + ((size_t)(b * S_ + sg)) * D_ + h * DH_ + 4 * cg) = v;
    }
}

// ---------------------------------------------------------------------------
// Launch
// ---------------------------------------------------------------------------
extern "C" void kernel_launch(void* const* d_in, const int* in_sizes, int n_in,
                              void* d_out, int out_size)
{
    (void)in_sizes; (void)n_in; (void)out_size;
    const float* x    = (const float*)d_in[0];
    const int*   mask = (const int*)  d_in[1];
    const float* Wq   = (const float*)d_in[2];
    const float* bq   = (const float*)d_in[3];
    const float* Wk   = (const float*)d_in[4];
    const float* bk   = (const float*)d_in[5];
    const float* Wv   = (const float*)d_in[6];
    const float* bv   = (const float*)d_in[7];
    const float* Wo   = (const float*)d_in[8];
    const float* bo   = (const float*)d_in[9];
    float* out = (float*)d_out;

    float *qp, *kp, *vp, *ap;
    cudaGetSymbolAddress((void**)&qp, g_q);
    cudaGetSymbolAddress((void**)&kp, g_k);
    cudaGetSymbolAddress((void**)&vp, g_v);
    cudaGetSymbolAddress((void**)&ap, g_att);

    static int attr_done = 0;
    if (!attr_done) {
        cudaFuncSetAttribute(flash_kernel,
                             cudaFuncAttributeMaxDynamicSharedMemorySize, FLASH_SMEM);
        attr_done = 1;
    }

    dim3 gg(D_ / 128, N_ / 128);   // (8, 32)
    gemm2<<<gg, 256>>>(x, Wq, bq, qp, 1);
    gemm2<<<gg, 256>>>(x, Wk, bk, kp, 1);
    gemm2<<<gg, 256>>>(x, Wv, bv, vp, 1);

    flash_kernel<<<dim3(S_ / 128, H_, B_), 256, FLASH_SMEM>>>(mask, ap);

    gemm2<<<gg, 256>>>(ap, Wo, bo, out, 0);
}